// round 2
// baseline (speedup 1.0000x reference)
#include <cuda_runtime.h>
#include <math.h>

#define NB 8
#define NH 512
#define NW 512
#define NP 32
#define HWC (NH*NW)
#define EPSF 1e-8f
#define INV2BW2 50.0f   /* 1/(2*0.1^2) */
#define NSEG 32
#define SEGROWS (NH/NSEG)   /* 16 */

/* ----- scratch (device globals; no allocations allowed) ----- */
__device__ float g_ex[NB*NP*NW];        /* exp(-(x_w-px)^2/2bw^2) */
__device__ float g_ey[NB*NP*NH];
__device__ float g_targ[NB*HWC];        /* 8 MB */
__device__ float g_diff[NB*HWC];        /* 8 MB: pred_n - targ_n */
__device__ float g_part_tsum[NB*NH];
__device__ float g_part_psum[NB*NH];
__device__ float g_invS[2*NB];          /* [0..7]=1/Spred, [8..15]=1/Starg */
__device__ float g_part_kl[NB*NH];
__device__ float g_part_emdw[NB*NH];
__device__ float g_part_emdh[NB*NSEG];
__device__ float g_colseg[NB*NSEG*NW];
__device__ float g_amax_pval[NB*NH];
__device__ int   g_amax_pidx[NB*NH];
__device__ float g_amax_tval[NB*NH];
__device__ int   g_amax_tidx[NB*NH];

/* ================= K1: separable gaussian factors ================= */
__global__ void k_exy(const float* __restrict__ pts) {
    int i = blockIdx.x * blockDim.x + threadIdx.x;      /* 0 .. NB*NP*NW-1 */
    if (i >= NB*NP*NW) return;
    int w  = i % NW;
    int bn = i / NW;                                    /* b*NP + n */
    float px = pts[bn*2 + 0];
    float py = pts[bn*2 + 1];
    float c  = (float)w * (1.0f/(float)(NW-1));         /* H==W so same coord */
    float dx = c - px;
    float dy = c - py;
    g_ex[i] = expf(-dx*dx*INV2BW2);
    g_ey[i] = expf(-dy*dy*INV2BW2);
}

/* ======== K2: target density (rank-32 outer product) + row sums ======== */
__global__ void k_density(const float* __restrict__ pred) {
    int blk = blockIdx.x;                 /* b*NH + h */
    int b = blk >> 9;
    int h = blk & (NH-1);
    int w = threadIdx.x;                  /* 512 threads */

    __shared__ float sEy[NP];
    if (w < NP) sEy[w] = g_ey[(b*NP + w)*NH + h];
    __syncthreads();

    const float* exb = &g_ex[b*NP*NW];
    float acc = 0.f;
#pragma unroll
    for (int n = 0; n < NP; n++) acc = fmaf(sEy[n], exb[n*NW + w], acc);

    int idx = blk*NW + w;
    g_targ[idx] = acc;
    float p = pred[idx];

    __shared__ float sr[NW];
    sr[w] = acc; __syncthreads();
#pragma unroll
    for (int s = 256; s > 0; s >>= 1) { if (w < s) sr[w] += sr[w+s]; __syncthreads(); }
    if (w == 0) g_part_tsum[blk] = sr[0];
    __syncthreads();
    sr[w] = p; __syncthreads();
#pragma unroll
    for (int s = 256; s > 0; s >>= 1) { if (w < s) sr[w] += sr[w+s]; __syncthreads(); }
    if (w == 0) g_part_psum[blk] = sr[0];
}

/* ================= K3: per-batch normalizers ================= */
__global__ void k_sums(const float* __restrict__ mask) {
    int t = threadIdx.x;                  /* 512 */
    __shared__ float sr[NH];
    for (int b = 0; b < NB; b++) {
        sr[t] = g_part_psum[b*NH + t]; __syncthreads();
#pragma unroll
        for (int s = 256; s > 0; s >>= 1) { if (t < s) sr[t] += sr[t+s]; __syncthreads(); }
        if (t == 0) {
            float S = mask[b]*sr[0] + (float)HWC*EPSF;
            g_invS[b] = 1.0f / S;
        }
        __syncthreads();
        sr[t] = g_part_tsum[b*NH + t]; __syncthreads();
#pragma unroll
        for (int s = 256; s > 0; s >>= 1) { if (t < s) sr[t] += sr[t+s]; __syncthreads(); }
        if (t == 0) {
            float S = mask[b]*sr[0] + (float)HWC*EPSF;
            g_invS[NB + b] = 1.0f / S;
        }
        __syncthreads();
    }
}

/* ==== K4: fused KL + diff store + EMD-along-W row scan + argmax partials ==== */
__global__ void k_main(const float* __restrict__ pred, const float* __restrict__ mask) {
    int blk = blockIdx.x;                 /* b*NH + h */
    int b = blk >> 9;
    int h = blk & (NH-1);
    int w = threadIdx.x;
    int idx = blk*NW + w;

    float m     = mask[b];
    float invSp = g_invS[b];
    float invSt = g_invS[NB + b];

    float p  = pred[idx]   * m;
    float t  = g_targ[idx] * m;
    float pn = (p + EPSF) * invSp;
    float tn = (t + EPSF) * invSt;
    float d  = pn - tn;
    g_diff[idx] = d;

    float kl = tn * (logf(tn) - logf(pn + EPSF));

    /* --- inclusive scan of d across the 512-wide row --- */
    int lane = w & 31, wid = w >> 5;
    float v = d;
#pragma unroll
    for (int off = 1; off < 32; off <<= 1) {
        float u = __shfl_up_sync(0xffffffffu, v, off);
        if (lane >= off) v += u;
    }
    __shared__ float swsum[16];
    __shared__ float swoff[16];
    if (lane == 31) swsum[wid] = v;
    __syncthreads();
    if (w < 16) {
        float x = swsum[w];
#pragma unroll
        for (int off = 1; off < 16; off <<= 1) {
            float u = __shfl_up_sync(0x0000ffffu, x, off);
            if (w >= off) x += u;
        }
        swoff[w] = x;
    }
    __syncthreads();
    float cum  = v + (wid > 0 ? swoff[wid-1] : 0.f);
    float aemd = fabsf(cum);

    /* --- block reductions --- */
    __shared__ float sr[NW];
    sr[w] = kl; __syncthreads();
#pragma unroll
    for (int s = 256; s > 0; s >>= 1) { if (w < s) sr[w] += sr[w+s]; __syncthreads(); }
    if (w == 0) g_part_kl[blk] = sr[0];
    __syncthreads();

    sr[w] = aemd; __syncthreads();
#pragma unroll
    for (int s = 256; s > 0; s >>= 1) { if (w < s) sr[w] += sr[w+s]; __syncthreads(); }
    if (w == 0) g_part_emdw[blk] = sr[0];
    __syncthreads();

    /* argmax (first-index tie-break) for pred*mask */
    __shared__ int si[NW];
    int fid = h*NW + w;
    sr[w] = p; si[w] = fid; __syncthreads();
#pragma unroll
    for (int s = 256; s > 0; s >>= 1) {
        if (w < s) {
            float a = sr[w], c = sr[w+s];
            if (c > a || (c == a && si[w+s] < si[w])) { sr[w] = c; si[w] = si[w+s]; }
        }
        __syncthreads();
    }
    if (w == 0) { g_amax_pval[blk] = sr[0]; g_amax_pidx[blk] = si[0]; }
    __syncthreads();

    /* argmax for targ*mask */
    sr[w] = t; si[w] = fid; __syncthreads();
#pragma unroll
    for (int s = 256; s > 0; s >>= 1) {
        if (w < s) {
            float a = sr[w], c = sr[w+s];
            if (c > a || (c == a && si[w+s] < si[w])) { sr[w] = c; si[w] = si[w+s]; }
        }
        __syncthreads();
    }
    if (w == 0) { g_amax_tval[blk] = sr[0]; g_amax_tidx[blk] = si[0]; }
}

/* ========== K5: per-segment column sums (EMD-along-H pass A) ========== */
__global__ void k_colseg() {
    int b   = blockIdx.x >> 5;
    int seg = blockIdx.x & (NSEG-1);
    int w   = threadIdx.x;
    const float* dptr = &g_diff[b*HWC + seg*SEGROWS*NW];
    float s = 0.f;
#pragma unroll
    for (int r = 0; r < SEGROWS; r++) s += dptr[r*NW + w];
    g_colseg[blockIdx.x*NW + w] = s;
}

/* ========== K6: EMD-along-H pass B (carry + local scan) ========== */
__global__ void k_emdh() {
    int b   = blockIdx.x >> 5;
    int seg = blockIdx.x & (NSEG-1);
    int w   = threadIdx.x;

    float carry = 0.f;
    for (int s2 = 0; s2 < seg; s2++) carry += g_colseg[(b*NSEG + s2)*NW + w];

    const float* dptr = &g_diff[b*HWC + seg*SEGROWS*NW];
    float c = carry, acc = 0.f;
#pragma unroll
    for (int r = 0; r < SEGROWS; r++) { c += dptr[r*NW + w]; acc += fabsf(c); }

    __shared__ float sr[NW];
    sr[w] = acc; __syncthreads();
#pragma unroll
    for (int s = 256; s > 0; s >>= 1) { if (w < s) sr[w] += sr[w+s]; __syncthreads(); }
    if (w == 0) g_part_emdh[blockIdx.x] = sr[0];
}

/* ================= K7: finalize ================= */
__global__ void k_final(float* __restrict__ out, int out_size) {
    int t = threadIdx.x;                  /* 512 */
    __shared__ float sr[NH];
    __shared__ int   si[NH];
    __shared__ float res_kl, res_ew, res_eh;
    __shared__ float ppx[NB], ppy[NB], tpx[NB], tpy[NB];

    /* KL sum over 4096 partials */
    float a = 0.f;
    for (int i = t; i < NB*NH; i += NH) a += g_part_kl[i];
    sr[t] = a; __syncthreads();
#pragma unroll
    for (int s = 256; s > 0; s >>= 1) { if (t < s) sr[t] += sr[t+s]; __syncthreads(); }
    if (t == 0) res_kl = sr[0];
    __syncthreads();

    /* EMD-W sum */
    a = 0.f;
    for (int i = t; i < NB*NH; i += NH) a += g_part_emdw[i];
    sr[t] = a; __syncthreads();
#pragma unroll
    for (int s = 256; s > 0; s >>= 1) { if (t < s) sr[t] += sr[t+s]; __syncthreads(); }
    if (t == 0) res_ew = sr[0];
    __syncthreads();

    /* EMD-H sum (256 partials) */
    a = (t < NB*NSEG) ? g_part_emdh[t] : 0.f;
    sr[t] = a; __syncthreads();
#pragma unroll
    for (int s = 256; s > 0; s >>= 1) { if (t < s) sr[t] += sr[t+s]; __syncthreads(); }
    if (t == 0) res_eh = sr[0];
    __syncthreads();

    /* per-batch argmax (val desc, idx asc) */
    for (int b = 0; b < NB; b++) {
        sr[t] = g_amax_pval[b*NH + t]; si[t] = g_amax_pidx[b*NH + t]; __syncthreads();
#pragma unroll
        for (int s = 256; s > 0; s >>= 1) {
            if (t < s) {
                float x = sr[t], c = sr[t+s];
                if (c > x || (c == x && si[t+s] < si[t])) { sr[t] = c; si[t] = si[t+s]; }
            }
            __syncthreads();
        }
        if (t == 0) {
            int id = si[0];
            ppy[b] = (float)(id / NW) * (1.0f/(float)(NH-1));
            ppx[b] = (float)(id % NW) * (1.0f/(float)(NW-1));
        }
        __syncthreads();
        sr[t] = g_amax_tval[b*NH + t]; si[t] = g_amax_tidx[b*NH + t]; __syncthreads();
#pragma unroll
        for (int s = 256; s > 0; s >>= 1) {
            if (t < s) {
                float x = sr[t], c = sr[t+s];
                if (c > x || (c == x && si[t+s] < si[t])) { sr[t] = c; si[t] = si[t+s]; }
            }
            __syncthreads();
        }
        if (t == 0) {
            int id = si[0];
            tpy[b] = (float)(id / NW) * (1.0f/(float)(NH-1));
            tpx[b] = (float)(id % NW) * (1.0f/(float)(NW-1));
        }
        __syncthreads();
    }

    if (t == 0) {
        float loss = res_kl * (1.0f/(float)NB);
        /* emd_h = sum_h/(B*H*W); emd_w = sum_w/(B*H*W); result = avg */
        float emd = (res_ew + res_eh) * (0.5f / ((float)NB * (float)HWC));
        int cnt = 0;
        for (int b = 0; b < NB; b++) {
            float dx = ppx[b]-tpx[b], dy = ppy[b]-tpy[b];
            float dist = sqrtf(dx*dx + dy*dy);
            if (dist < 0.1f) cnt++;
        }
        float acc = (float)cnt * (1.0f/(float)NB);
        if (out_size > 0) out[0] = loss;
        if (out_size > 1) out[1] = emd;
        if (out_size > 2) out[2] = acc;
    }
}

extern "C" void kernel_launch(void* const* d_in, const int* in_sizes, int n_in,
                              void* d_out, int out_size) {
    const float* pred = (const float*)d_in[0];   /* [8,512,512] */
    const float* pts  = (const float*)d_in[1];   /* [8,32,2]    */
    const float* mask = (const float*)d_in[2];   /* [8]         */
    float* out = (float*)d_out;

    k_exy<<<(NB*NP*NW + 255)/256, 256>>>(pts);
    k_density<<<NB*NH, NW>>>(pred);
    k_sums<<<1, NH>>>(mask);
    k_main<<<NB*NH, NW>>>(pred, mask);
    k_colseg<<<NB*NSEG, NW>>>();
    k_emdh<<<NB*NSEG, NW>>>();
    k_final<<<1, NH>>>(out, out_size);
}

// round 3
// speedup vs baseline: 3.6523x; 3.6523x over previous
#include <cuda_runtime.h>
#include <math.h>

#define NB 8
#define NH 512
#define NW 512
#define NP 32
#define HWC (NH*NW)
#define EPSF 1e-8f
#define INV2BW2 50.0f
#define NSEG 32
#define SEGROWS 16          /* NH/NSEG */
#define PSPLIT 8

/* ---------------- scratch (device globals) ---------------- */
__device__ float g_ex[NB*NP*NW];
__device__ float g_ey[NB*NP*NH];
__device__ float g_sx[NB*NP];
__device__ float g_sy[NB*NP];
__device__ float g_psum_part[NB*PSPLIT];
__device__ float g_invS[2*NB];          /* [0..7]=1/Spred, [8..15]=1/Starg */
__device__ float g_diff[NB*HWC];        /* 8 MB */
__device__ float g_colseg[NB*NSEG*NW];
__device__ float g_part_kl[NB*NSEG];
__device__ float g_part_emdw[NB*NSEG];
__device__ float g_part_emdh[NB*NSEG];
__device__ float g_amax_pval[NB*NSEG];
__device__ int   g_amax_pidx[NB*NSEG];
__device__ float g_amax_tval[NB*NSEG];
__device__ int   g_amax_tidx[NB*NSEG];

/* ===== K1: separable gaussian factors + their 1-D sums ===== */
__global__ __launch_bounds__(512) void k_exy(const float* __restrict__ pts) {
    int bn = blockIdx.x;                  /* b*NP+n, 256 blocks */
    int w  = threadIdx.x;                 /* 512 */
    int lane = w & 31, wid = w >> 5;
    float px = pts[bn*2 + 0];
    float py = pts[bn*2 + 1];
    float c  = (float)w * (1.0f/511.0f);
    float dx = c - px, dy = c - py;
    float ex = __expf(-dx*dx*INV2BW2);
    float ey = __expf(-dy*dy*INV2BW2);
    g_ex[bn*NW + w] = ex;
    g_ey[bn*NH + w] = ey;

    __shared__ float sred[16];
    float v = ex;
#pragma unroll
    for (int off = 16; off; off >>= 1) v += __shfl_xor_sync(~0u, v, off);
    if (lane == 0) sred[wid] = v;
    __syncthreads();
    if (w == 0) { float s = 0.f;
#pragma unroll
        for (int j = 0; j < 16; j++) s += sred[j];
        g_sx[bn] = s; }
    __syncthreads();
    v = ey;
#pragma unroll
    for (int off = 16; off; off >>= 1) v += __shfl_xor_sync(~0u, v, off);
    if (lane == 0) sred[wid] = v;
    __syncthreads();
    if (w == 0) { float s = 0.f;
#pragma unroll
        for (int j = 0; j < 16; j++) s += sred[j];
        g_sy[bn] = s; }
}

/* ===== K2: per-batch pred sums (8 partials per batch) ===== */
__global__ __launch_bounds__(256) void k_psum(const float4* __restrict__ pred4) {
    int blk = blockIdx.x;                 /* 64 blocks: b*8+part */
    int t = threadIdx.x;                  /* 256 */
    int lane = t & 31, wid = t >> 5;
    const float4* p = pred4 + blk * 8192;
    float s = 0.f;
#pragma unroll 8
    for (int i = 0; i < 32; i++) {
        float4 v = p[t + i*256];
        s += (v.x + v.y) + (v.z + v.w);
    }
#pragma unroll
    for (int off = 16; off; off >>= 1) s += __shfl_xor_sync(~0u, s, off);
    __shared__ float sred[8];
    if (lane == 0) sred[wid] = s;
    __syncthreads();
    if (t == 0) { float a = 0.f;
#pragma unroll
        for (int j = 0; j < 8; j++) a += sred[j];
        g_psum_part[blk] = a; }
}

/* ===== K3: normalizers (tiny) ===== */
__global__ void k_norm(const float* __restrict__ mask) {
    int b = threadIdx.x;
    if (b >= NB) return;
    float ps = 0.f;
#pragma unroll
    for (int j = 0; j < PSPLIT; j++) ps += g_psum_part[b*PSPLIT + j];
    float ts = 0.f;
#pragma unroll
    for (int n = 0; n < NP; n++) ts += g_sx[b*NP+n] * g_sy[b*NP+n];
    float m = mask[b];
    g_invS[b]      = 1.0f / (m*ps + (float)HWC*EPSF);
    g_invS[NB + b] = 1.0f / (m*ts + (float)HWC*EPSF);
}

/* ===== K4: fused density + KL + diff + EMD-W scans + col sums + argmax ===== */
__global__ __launch_bounds__(512) void k_main(const float* __restrict__ pred,
                                              const float* __restrict__ mask) {
    int blk = blockIdx.x;                 /* b*NSEG+seg, 256 blocks */
    int b = blk >> 5, seg = blk & 31;
    int w = threadIdx.x, lane = w & 31, wid = w >> 5;

    __shared__ float sEy[SEGROWS*NP];     /* [r][n] */
    __shared__ float swsum[2][16];
    __shared__ float sred[16];
    __shared__ int   sidx[16];

    { /* load ey broadcast table: thread -> (r = w>>5, n = w&31) */
        int r = w >> 5, n = w & 31;
        sEy[r*NP + n] = g_ey[(b*NP + n)*NH + seg*SEGROWS + r];
    }
    float rex[NP];                        /* ex column in registers */
#pragma unroll
    for (int n = 0; n < NP; n++) rex[n] = g_ex[(b*NP + n)*NW + w];

    float m     = mask[b];
    float invSp = g_invS[b];
    float invSt = g_invS[NB + b];
    __syncthreads();

    float klacc = 0.f, ewacc = 0.f, ccol = 0.f;
    float apv = -1e30f, atv = -1e30f;
    int   api = 0, ati = 0;
    int rowbase = (b*NH + seg*SEGROWS)*NW + w;

#pragma unroll 2
    for (int r = 0; r < SEGROWS; r++) {
        float p = __ldg(&pred[rowbase + r*NW]);
        float acc = 0.f;
#pragma unroll
        for (int n = 0; n < NP; n++) acc = fmaf(sEy[r*NP + n], rex[n], acc);
        float pm = p * m, tm = acc * m;
        float pn = (pm + EPSF) * invSp;
        float tn = (tm + EPSF) * invSt;
        float d  = pn - tn;
        g_diff[rowbase + r*NW] = d;
        klacc = fmaf(tn, __logf(__fdividef(tn, pn + EPSF)), klacc);
        ccol += d;
        int fid = (seg*SEGROWS + r)*NW + w;
        if (pm > apv) { apv = pm; api = fid; }
        if (tm > atv) { atv = tm; ati = fid; }
        /* row-wide inclusive scan of d (1 barrier per row) */
        float v = d;
#pragma unroll
        for (int off = 1; off < 32; off <<= 1) {
            float u = __shfl_up_sync(~0u, v, off);
            if (lane >= off) v += u;
        }
        if (lane == 31) swsum[r & 1][wid] = v;
        __syncthreads();
        float offacc = 0.f;
        for (int j = 0; j < wid; j++) offacc += swsum[r & 1][j];
        ewacc += fabsf(v + offacc);
    }
    g_colseg[blk*NW + w] = ccol;

    /* --- block reductions via shuffles --- */
    float v = klacc;
#pragma unroll
    for (int off = 16; off; off >>= 1) v += __shfl_xor_sync(~0u, v, off);
    if (lane == 0) sred[wid] = v;
    __syncthreads();
    if (w == 0) { float s = 0.f;
#pragma unroll
        for (int j = 0; j < 16; j++) s += sred[j];
        g_part_kl[blk] = s; }
    __syncthreads();

    v = ewacc;
#pragma unroll
    for (int off = 16; off; off >>= 1) v += __shfl_xor_sync(~0u, v, off);
    if (lane == 0) sred[wid] = v;
    __syncthreads();
    if (w == 0) { float s = 0.f;
#pragma unroll
        for (int j = 0; j < 16; j++) s += sred[j];
        g_part_emdw[blk] = s; }
    __syncthreads();

    /* argmax pred (val desc, idx asc) */
    float av = apv; int ai = api;
#pragma unroll
    for (int off = 16; off; off >>= 1) {
        float ov = __shfl_xor_sync(~0u, av, off);
        int   oi = __shfl_xor_sync(~0u, ai, off);
        if (ov > av || (ov == av && oi < ai)) { av = ov; ai = oi; }
    }
    if (lane == 0) { sred[wid] = av; sidx[wid] = ai; }
    __syncthreads();
    if (w == 0) {
        float bv = sred[0]; int bi = sidx[0];
#pragma unroll
        for (int j = 1; j < 16; j++) {
            if (sred[j] > bv || (sred[j] == bv && sidx[j] < bi)) { bv = sred[j]; bi = sidx[j]; }
        }
        g_amax_pval[blk] = bv; g_amax_pidx[blk] = bi;
    }
    __syncthreads();

    /* argmax targ */
    av = atv; ai = ati;
#pragma unroll
    for (int off = 16; off; off >>= 1) {
        float ov = __shfl_xor_sync(~0u, av, off);
        int   oi = __shfl_xor_sync(~0u, ai, off);
        if (ov > av || (ov == av && oi < ai)) { av = ov; ai = oi; }
    }
    if (lane == 0) { sred[wid] = av; sidx[wid] = ai; }
    __syncthreads();
    if (w == 0) {
        float bv = sred[0]; int bi = sidx[0];
#pragma unroll
        for (int j = 1; j < 16; j++) {
            if (sred[j] > bv || (sred[j] == bv && sidx[j] < bi)) { bv = sred[j]; bi = sidx[j]; }
        }
        g_amax_tval[blk] = bv; g_amax_tidx[blk] = bi;
    }
}

/* ===== K5: EMD-along-H (carry from colseg + local column scan) ===== */
__global__ __launch_bounds__(512) void k_emdh() {
    int blk = blockIdx.x;                 /* b*NSEG+seg */
    int b = blk >> 5, seg = blk & 31;
    int w = threadIdx.x, lane = w & 31, wid = w >> 5;

    float carry = 0.f;
    for (int s2 = 0; s2 < seg; s2++) carry += g_colseg[(b*NSEG + s2)*NW + w];

    const float* dptr = &g_diff[(b*NH + seg*SEGROWS)*NW + w];
    float c = carry, acc = 0.f;
#pragma unroll
    for (int r = 0; r < SEGROWS; r++) { c += dptr[r*NW]; acc += fabsf(c); }

#pragma unroll
    for (int off = 16; off; off >>= 1) acc += __shfl_xor_sync(~0u, acc, off);
    __shared__ float sred[16];
    if (lane == 0) sred[wid] = acc;
    __syncthreads();
    if (w == 0) { float s = 0.f;
#pragma unroll
        for (int j = 0; j < 16; j++) s += sred[j];
        g_part_emdh[blk] = s; }
}

/* ===== K6: finalize ===== */
__global__ __launch_bounds__(256) void k_final(float* __restrict__ out, int out_size) {
    int t = threadIdx.x;                  /* 256 */
    int lane = t & 31, wid = t >> 5;
    __shared__ float sred[8];
    __shared__ float res3[3];             /* kl, emdw, emdh */
    __shared__ float ppx[NB], ppy[NB], tpx[NB], tpy[NB];

    const float* srcs[3] = { g_part_kl, g_part_emdw, g_part_emdh };
    for (int k = 0; k < 3; k++) {
        float v = srcs[k][t];
#pragma unroll
        for (int off = 16; off; off >>= 1) v += __shfl_xor_sync(~0u, v, off);
        if (lane == 0) sred[wid] = v;
        __syncthreads();
        if (t == 0) { float s = 0.f;
#pragma unroll
            for (int j = 0; j < 8; j++) s += sred[j];
            res3[k] = s; }
        __syncthreads();
    }

    /* per-batch argmax: warp wid handles batch wid (8 warps, 32 partials each) */
    {
        float av = g_amax_pval[t]; int ai = g_amax_pidx[t];
#pragma unroll
        for (int off = 16; off; off >>= 1) {
            float ov = __shfl_xor_sync(~0u, av, off);
            int   oi = __shfl_xor_sync(~0u, ai, off);
            if (ov > av || (ov == av && oi < ai)) { av = ov; ai = oi; }
        }
        if (lane == 0) {
            ppy[wid] = (float)(ai / NW) * (1.0f/511.0f);
            ppx[wid] = (float)(ai % NW) * (1.0f/511.0f);
        }
        av = g_amax_tval[t]; ai = g_amax_tidx[t];
#pragma unroll
        for (int off = 16; off; off >>= 1) {
            float ov = __shfl_xor_sync(~0u, av, off);
            int   oi = __shfl_xor_sync(~0u, ai, off);
            if (ov > av || (ov == av && oi < ai)) { av = ov; ai = oi; }
        }
        if (lane == 0) {
            tpy[wid] = (float)(ai / NW) * (1.0f/511.0f);
            tpx[wid] = (float)(ai % NW) * (1.0f/511.0f);
        }
    }
    __syncthreads();

    if (t == 0) {
        float loss = res3[0] * (1.0f/(float)NB);
        float emd  = (res3[1] + res3[2]) * (0.5f / ((float)NB * (float)HWC));
        int cnt = 0;
        for (int b = 0; b < NB; b++) {
            float dx = ppx[b]-tpx[b], dy = ppy[b]-tpy[b];
            if (sqrtf(dx*dx + dy*dy) < 0.1f) cnt++;
        }
        float acc = (float)cnt * (1.0f/(float)NB);
        if (out_size > 0) out[0] = loss;
        if (out_size > 1) out[1] = emd;
        if (out_size > 2) out[2] = acc;
    }
}

extern "C" void kernel_launch(void* const* d_in, const int* in_sizes, int n_in,
                              void* d_out, int out_size) {
    const float* pred = (const float*)d_in[0];   /* [8,512,512] */
    const float* pts  = (const float*)d_in[1];   /* [8,32,2]    */
    const float* mask = (const float*)d_in[2];   /* [8]         */
    float* out = (float*)d_out;

    k_exy<<<NB*NP, 512>>>(pts);
    k_psum<<<NB*PSPLIT, 256>>>((const float4*)pred);
    k_norm<<<1, 32>>>(mask);
    k_main<<<NB*NSEG, 512>>>(pred, mask);
    k_emdh<<<NB*NSEG, 512>>>();
    k_final<<<1, 256>>>(out, out_size);
}

// round 4
// speedup vs baseline: 4.1268x; 1.1299x over previous
#include <cuda_runtime.h>
#include <math.h>

#define NB 8
#define NH 512
#define NW 512
#define NP 32
#define HWC (NH*NW)
#define EPSF 1e-8f
#define INV2BW2 50.0f
#define NSEG 32
#define SEGROWS 16
#define PSPLIT 8
#define SDSTRIDE 520        /* 512 + skew room */

/* ---------------- scratch (device globals) ---------------- */
__device__ float g_ex[NB*NP*NW];
__device__ float g_ey[NB*NP*NH];
__device__ float g_sx[NB*NP];
__device__ float g_sy[NB*NP];
__device__ float g_psum_part[NB*PSPLIT];
__device__ float g_invS[2*NB];
__device__ float g_diff[NB*HWC];        /* 8 MB */
__device__ float g_colseg[NB*NSEG*NW];  /* becomes exclusive carry after k_carry */
__device__ float g_part_kl[NB*NSEG];
__device__ float g_part_emdw[NB*NSEG];
__device__ float g_part_emdh[NB*NSEG];
__device__ float g_amax_pval[NB*NSEG];
__device__ int   g_amax_pidx[NB*NSEG];
__device__ float g_amax_tval[NB*NSEG];
__device__ int   g_amax_tidx[NB*NSEG];

/* ===== K1: fused (a) gaussian factors + 1-D sums, (b) pred partial sums ===== */
__global__ __launch_bounds__(512) void k_prep(const float* __restrict__ pts,
                                              const float4* __restrict__ pred4) {
    int blk = blockIdx.x;
    int t = threadIdx.x, lane = t & 31, wid = t >> 5;
    __shared__ float sred[16];

    if (blk < NB*NP) {                    /* gaussian factor blocks */
        int bn = blk;
        float px = pts[bn*2 + 0];
        float py = pts[bn*2 + 1];
        float c  = (float)t * (1.0f/511.0f);
        float dx = c - px, dy = c - py;
        float ex = __expf(-dx*dx*INV2BW2);
        float ey = __expf(-dy*dy*INV2BW2);
        g_ex[bn*NW + t] = ex;
        g_ey[bn*NH + t] = ey;

        float v = ex;
#pragma unroll
        for (int off = 16; off; off >>= 1) v += __shfl_xor_sync(~0u, v, off);
        if (lane == 0) sred[wid] = v;
        __syncthreads();
        if (t == 0) { float s = 0.f;
#pragma unroll
            for (int j = 0; j < 16; j++) s += sred[j];
            g_sx[bn] = s; }
        __syncthreads();
        v = ey;
#pragma unroll
        for (int off = 16; off; off >>= 1) v += __shfl_xor_sync(~0u, v, off);
        if (lane == 0) sred[wid] = v;
        __syncthreads();
        if (t == 0) { float s = 0.f;
#pragma unroll
            for (int j = 0; j < 16; j++) s += sred[j];
            g_sy[bn] = s; }
    } else {                              /* pred partial-sum blocks */
        int part = blk - NB*NP;           /* 0..63 */
        const float4* p = pred4 + part * 8192;
        float s = 0.f;
#pragma unroll 4
        for (int i = 0; i < 16; i++) {
            float4 v = p[t + i*512];
            s += (v.x + v.y) + (v.z + v.w);
        }
#pragma unroll
        for (int off = 16; off; off >>= 1) s += __shfl_xor_sync(~0u, s, off);
        if (lane == 0) sred[wid] = s;
        __syncthreads();
        if (t == 0) { float a = 0.f;
#pragma unroll
            for (int j = 0; j < 16; j++) a += sred[j];
            g_psum_part[part] = a; }
    }
}

/* ===== K2: normalizers (tiny) ===== */
__global__ void k_norm(const float* __restrict__ mask) {
    int b = threadIdx.x;
    if (b >= NB) return;
    float ps = 0.f;
#pragma unroll
    for (int j = 0; j < PSPLIT; j++) ps += g_psum_part[b*PSPLIT + j];
    float ts = 0.f;
#pragma unroll
    for (int n = 0; n < NP; n++) ts += g_sx[b*NP+n] * g_sy[b*NP+n];
    float m = mask[b];
    g_invS[b]      = 1.0f / (m*ps + (float)HWC*EPSF);
    g_invS[NB + b] = 1.0f / (m*ts + (float)HWC*EPSF);
}

/* ===== K3: fused density + KL + diff + EMD-W (warp-per-row scan) + argmax ===== */
__global__ __launch_bounds__(512, 2) void k_main(const float* __restrict__ pred,
                                                 const float* __restrict__ mask) {
    int blk = blockIdx.x;                 /* b*NSEG+seg, 256 blocks */
    int b = blk >> 5, seg = blk & 31;
    int w = threadIdx.x, lane = w & 31, wid = w >> 5;

    __shared__ float sEy[SEGROWS*NP];
    __shared__ float sD[SEGROWS*SDSTRIDE];
    __shared__ float sred[16];
    __shared__ int   sidx[16];

    /* ey broadcast table: thread -> (r = w>>5, n = w&31) */
    sEy[(w >> 5)*NP + (w & 31)] = g_ey[(b*NP + (w & 31))*NH + seg*SEGROWS + (w >> 5)];

    float rex[NP];
#pragma unroll
    for (int n = 0; n < NP; n++) rex[n] = g_ex[(b*NP + n)*NW + w];

    float m     = mask[b];
    float invSp = g_invS[b];
    float invSt = g_invS[NB + b];
    __syncthreads();

    float klacc = 0.f, ccol = 0.f;
    float apv = -1e30f, atv = -1e30f;
    int   api = 0, ati = 0;
    int rowbase = (b*NH + seg*SEGROWS)*NW + w;
    int skw = w + (w >> 4);               /* skewed smem column */

#pragma unroll 4
    for (int r = 0; r < SEGROWS; r++) {
        float p = __ldg(&pred[rowbase + r*NW]);
        float acc = 0.f;
#pragma unroll
        for (int n = 0; n < NP; n++) acc = fmaf(sEy[r*NP + n], rex[n], acc);
        float pm = p * m, tm = acc * m;
        float pn = (pm + EPSF) * invSp;
        float tn = (tm + EPSF) * invSt;
        float d  = pn - tn;
        g_diff[rowbase + r*NW] = d;
        sD[r*SDSTRIDE + skw] = d;
        klacc = fmaf(tn, __logf(__fdividef(tn, pn + EPSF)), klacc);
        ccol += d;
        int fid = (seg*SEGROWS + r)*NW + w;
        if (pm > apv) { apv = pm; api = fid; }
        if (tm > atv) { atv = tm; ati = fid; }
    }
    g_colseg[blk*NW + w] = ccol;
    __syncthreads();

    /* --- EMD-W: warp `wid` scans row `wid`; lane owns 16 contiguous elems --- */
    float ewacc;
    {
        float vals[16];
        int base = wid*SDSTRIDE + lane*17;     /* 16*lane + (16*lane>>4) = 17*lane */
        float s = 0.f;
#pragma unroll
        for (int i = 0; i < 16; i++) { vals[i] = sD[base + i]; s += vals[i]; }
        float incl = s;
#pragma unroll
        for (int off = 1; off < 32; off <<= 1) {
            float u = __shfl_up_sync(~0u, incl, off);
            if (lane >= off) incl += u;
        }
        float run = incl - s;                  /* exclusive prefix */
        ewacc = 0.f;
#pragma unroll
        for (int i = 0; i < 16; i++) { run += vals[i]; ewacc += fabsf(run); }
    }

    /* --- block reductions via shuffles --- */
    float v = klacc;
#pragma unroll
    for (int off = 16; off; off >>= 1) v += __shfl_xor_sync(~0u, v, off);
    if (lane == 0) sred[wid] = v;
    __syncthreads();
    if (w == 0) { float s = 0.f;
#pragma unroll
        for (int j = 0; j < 16; j++) s += sred[j];
        g_part_kl[blk] = s; }
    __syncthreads();

    v = ewacc;
#pragma unroll
    for (int off = 16; off; off >>= 1) v += __shfl_xor_sync(~0u, v, off);
    if (lane == 0) sred[wid] = v;
    __syncthreads();
    if (w == 0) { float s = 0.f;
#pragma unroll
        for (int j = 0; j < 16; j++) s += sred[j];
        g_part_emdw[blk] = s; }
    __syncthreads();

    /* argmax pred (val desc, idx asc) */
    float av = apv; int ai = api;
#pragma unroll
    for (int off = 16; off; off >>= 1) {
        float ov = __shfl_xor_sync(~0u, av, off);
        int   oi = __shfl_xor_sync(~0u, ai, off);
        if (ov > av || (ov == av && oi < ai)) { av = ov; ai = oi; }
    }
    if (lane == 0) { sred[wid] = av; sidx[wid] = ai; }
    __syncthreads();
    if (w == 0) {
        float bv = sred[0]; int bi = sidx[0];
#pragma unroll
        for (int j = 1; j < 16; j++)
            if (sred[j] > bv || (sred[j] == bv && sidx[j] < bi)) { bv = sred[j]; bi = sidx[j]; }
        g_amax_pval[blk] = bv; g_amax_pidx[blk] = bi;
    }
    __syncthreads();

    /* argmax targ */
    av = atv; ai = ati;
#pragma unroll
    for (int off = 16; off; off >>= 1) {
        float ov = __shfl_xor_sync(~0u, av, off);
        int   oi = __shfl_xor_sync(~0u, ai, off);
        if (ov > av || (ov == av && oi < ai)) { av = ov; ai = oi; }
    }
    if (lane == 0) { sred[wid] = av; sidx[wid] = ai; }
    __syncthreads();
    if (w == 0) {
        float bv = sred[0]; int bi = sidx[0];
#pragma unroll
        for (int j = 1; j < 16; j++)
            if (sred[j] > bv || (sred[j] == bv && sidx[j] < bi)) { bv = sred[j]; bi = sidx[j]; }
        g_amax_tval[blk] = bv; g_amax_tidx[blk] = bi;
    }
}

/* ===== K4: turn per-segment column sums into exclusive carries (in place) ===== */
__global__ __launch_bounds__(512) void k_carry() {
    int b = blockIdx.x;                   /* 8 blocks */
    int w = threadIdx.x;
    float run = 0.f;
#pragma unroll 4
    for (int s = 0; s < NSEG; s++) {
        int idx = (b*NSEG + s)*NW + w;
        float v = g_colseg[idx];
        g_colseg[idx] = run;
        run += v;
    }
}

/* ===== K5: EMD-along-H (carry + local column scan) ===== */
__global__ __launch_bounds__(512) void k_emdh() {
    int blk = blockIdx.x;                 /* b*NSEG+seg */
    int b = blk >> 5, seg = blk & 31;
    int w = threadIdx.x, lane = w & 31, wid = w >> 5;

    float c = g_colseg[blk*NW + w];       /* exclusive carry */
    const float* dptr = &g_diff[(b*NH + seg*SEGROWS)*NW + w];
    float acc = 0.f;
#pragma unroll
    for (int r = 0; r < SEGROWS; r++) { c += dptr[r*NW]; acc += fabsf(c); }

#pragma unroll
    for (int off = 16; off; off >>= 1) acc += __shfl_xor_sync(~0u, acc, off);
    __shared__ float sred[16];
    if (lane == 0) sred[wid] = acc;
    __syncthreads();
    if (w == 0) { float s = 0.f;
#pragma unroll
        for (int j = 0; j < 16; j++) s += sred[j];
        g_part_emdh[blk] = s; }
}

/* ===== K6: finalize ===== */
__global__ __launch_bounds__(256) void k_final(float* __restrict__ out, int out_size) {
    int t = threadIdx.x;                  /* 256 */
    int lane = t & 31, wid = t >> 5;
    __shared__ float sred[8];
    __shared__ float res3[3];
    __shared__ float ppx[NB], ppy[NB], tpx[NB], tpy[NB];

    const float* srcs[3] = { g_part_kl, g_part_emdw, g_part_emdh };
    for (int k = 0; k < 3; k++) {
        float v = srcs[k][t];
#pragma unroll
        for (int off = 16; off; off >>= 1) v += __shfl_xor_sync(~0u, v, off);
        if (lane == 0) sred[wid] = v;
        __syncthreads();
        if (t == 0) { float s = 0.f;
#pragma unroll
            for (int j = 0; j < 8; j++) s += sred[j];
            res3[k] = s; }
        __syncthreads();
    }

    /* per-batch argmax: warp wid handles batch wid */
    {
        float av = g_amax_pval[t]; int ai = g_amax_pidx[t];
#pragma unroll
        for (int off = 16; off; off >>= 1) {
            float ov = __shfl_xor_sync(~0u, av, off);
            int   oi = __shfl_xor_sync(~0u, ai, off);
            if (ov > av || (ov == av && oi < ai)) { av = ov; ai = oi; }
        }
        if (lane == 0) {
            ppy[wid] = (float)(ai / NW) * (1.0f/511.0f);
            ppx[wid] = (float)(ai % NW) * (1.0f/511.0f);
        }
        av = g_amax_tval[t]; ai = g_amax_tidx[t];
#pragma unroll
        for (int off = 16; off; off >>= 1) {
            float ov = __shfl_xor_sync(~0u, av, off);
            int   oi = __shfl_xor_sync(~0u, ai, off);
            if (ov > av || (ov == av && oi < ai)) { av = ov; ai = oi; }
        }
        if (lane == 0) {
            tpy[wid] = (float)(ai / NW) * (1.0f/511.0f);
            tpx[wid] = (float)(ai % NW) * (1.0f/511.0f);
        }
    }
    __syncthreads();

    if (t == 0) {
        float loss = res3[0] * (1.0f/(float)NB);
        float emd  = (res3[1] + res3[2]) * (0.5f / ((float)NB * (float)HWC));
        int cnt = 0;
        for (int b = 0; b < NB; b++) {
            float dx = ppx[b]-tpx[b], dy = ppy[b]-tpy[b];
            if (sqrtf(dx*dx + dy*dy) < 0.1f) cnt++;
        }
        float acc = (float)cnt * (1.0f/(float)NB);
        if (out_size > 0) out[0] = loss;
        if (out_size > 1) out[1] = emd;
        if (out_size > 2) out[2] = acc;
    }
}

extern "C" void kernel_launch(void* const* d_in, const int* in_sizes, int n_in,
                              void* d_out, int out_size) {
    const float* pred = (const float*)d_in[0];   /* [8,512,512] */
    const float* pts  = (const float*)d_in[1];   /* [8,32,2]    */
    const float* mask = (const float*)d_in[2];   /* [8]         */
    float* out = (float*)d_out;

    k_prep<<<NB*NP + NB*PSPLIT, 512>>>(pts, (const float4*)pred);
    k_norm<<<1, 32>>>(mask);
    k_main<<<NB*NSEG, 512>>>(pred, mask);
    k_carry<<<NB, 512>>>();
    k_emdh<<<NB*NSEG, 512>>>();
    k_final<<<1, 256>>>(out, out_size);
}

// round 5
// speedup vs baseline: 4.4308x; 1.0737x over previous
#include <cuda_runtime.h>
#include <math.h>

#define NB 8
#define NH 512
#define NW 512
#define NP 32
#define HWC (NH*NW)
#define EPSF 1e-8f
#define INV2BW2 50.0f
#define NSEG 32
#define SEGROWS 16
#define PSPLIT 8
#define SDSTRIDE 520        /* 512 + skew room */

/* ---------------- scratch (device globals) ---------------- */
__device__ float  g_ex[NB*NP*NW];
__device__ float  g_ey[NB*NP*NH];
__device__ float  g_sx[NB*NP];
__device__ float  g_sy[NB*NP];
__device__ float  g_psum_part[NB*PSPLIT];
__device__ float  g_invS[2*NB];
__device__ float  g_diff[NB*HWC];        /* 8 MB */
__device__ double g_colseg[NB*NSEG*NW];  /* per-segment column sums (1 MB) */
__device__ double g_part_kl[NB*NSEG];
__device__ double g_part_emdw[NB*NSEG];
__device__ double g_part_emdh[NB*NSEG];
__device__ float  g_amax_pval[NB*NSEG];
__device__ int    g_amax_pidx[NB*NSEG];
__device__ float  g_amax_tval[NB*NSEG];
__device__ int    g_amax_tidx[NB*NSEG];

/* ===== K1: fused (a) gaussian factors + 1-D sums, (b) pred partial sums ===== */
__global__ __launch_bounds__(512) void k_prep(const float* __restrict__ pts,
                                              const float4* __restrict__ pred4) {
    int blk = blockIdx.x;
    int t = threadIdx.x, lane = t & 31, wid = t >> 5;
    __shared__ float sred[16];

    if (blk < NB*NP) {                    /* gaussian factor blocks */
        int bn = blk;
        float px = pts[bn*2 + 0];
        float py = pts[bn*2 + 1];
        float c  = (float)t * (1.0f/511.0f);
        float dx = c - px, dy = c - py;
        float ex = __expf(-dx*dx*INV2BW2);
        float ey = __expf(-dy*dy*INV2BW2);
        g_ex[bn*NW + t] = ex;
        g_ey[bn*NH + t] = ey;

        float v = ex;
#pragma unroll
        for (int off = 16; off; off >>= 1) v += __shfl_xor_sync(~0u, v, off);
        if (lane == 0) sred[wid] = v;
        __syncthreads();
        if (t == 0) { float s = 0.f;
#pragma unroll
            for (int j = 0; j < 16; j++) s += sred[j];
            g_sx[bn] = s; }
        __syncthreads();
        v = ey;
#pragma unroll
        for (int off = 16; off; off >>= 1) v += __shfl_xor_sync(~0u, v, off);
        if (lane == 0) sred[wid] = v;
        __syncthreads();
        if (t == 0) { float s = 0.f;
#pragma unroll
            for (int j = 0; j < 16; j++) s += sred[j];
            g_sy[bn] = s; }
    } else {                              /* pred partial-sum blocks */
        int part = blk - NB*NP;           /* 0..63 */
        const float4* p = pred4 + part * 8192;
        float s = 0.f;
#pragma unroll 4
        for (int i = 0; i < 16; i++) {
            float4 v = p[t + i*512];
            s += (v.x + v.y) + (v.z + v.w);
        }
#pragma unroll
        for (int off = 16; off; off >>= 1) s += __shfl_xor_sync(~0u, s, off);
        if (lane == 0) sred[wid] = s;
        __syncthreads();
        if (t == 0) { float a = 0.f;
#pragma unroll
            for (int j = 0; j < 16; j++) a += sred[j];
            g_psum_part[part] = a; }
    }
}

/* ===== K2: normalizers (tiny) ===== */
__global__ void k_norm(const float* __restrict__ mask) {
    int b = threadIdx.x;
    if (b >= NB) return;
    float ps = 0.f;
#pragma unroll
    for (int j = 0; j < PSPLIT; j++) ps += g_psum_part[b*PSPLIT + j];
    float ts = 0.f;
#pragma unroll
    for (int n = 0; n < NP; n++) ts += g_sx[b*NP+n] * g_sy[b*NP+n];
    float m = mask[b];
    g_invS[b]      = 1.0f / (m*ps + (float)HWC*EPSF);
    g_invS[NB + b] = 1.0f / (m*ts + (float)HWC*EPSF);
}

/* ===== K3: fused density + KL + diff + EMD-W (warp-per-row, fp64 scan) + argmax ===== */
__global__ __launch_bounds__(512, 2) void k_main(const float* __restrict__ pred,
                                                 const float* __restrict__ mask) {
    int blk = blockIdx.x;                 /* b*NSEG+seg, 256 blocks */
    int b = blk >> 5, seg = blk & 31;
    int w = threadIdx.x, lane = w & 31, wid = w >> 5;

    __shared__ float  sEy[SEGROWS*NP];
    __shared__ float  sD[SEGROWS*SDSTRIDE];
    __shared__ float  sred[16];
    __shared__ double sredd[16];
    __shared__ int    sidx[16];

    sEy[(w >> 5)*NP + (w & 31)] = g_ey[(b*NP + (w & 31))*NH + seg*SEGROWS + (w >> 5)];

    float rex[NP];
#pragma unroll
    for (int n = 0; n < NP; n++) rex[n] = g_ex[(b*NP + n)*NW + w];

    float m     = mask[b];
    float invSp = g_invS[b];
    float invSt = g_invS[NB + b];
    __syncthreads();

    float  klacc = 0.f;
    double ccol  = 0.0;
    float apv = -1e30f, atv = -1e30f;
    int   api = 0, ati = 0;
    int rowbase = (b*NH + seg*SEGROWS)*NW + w;
    int skw = w + (w >> 4);               /* skewed smem column */

#pragma unroll 4
    for (int r = 0; r < SEGROWS; r++) {
        float p = __ldg(&pred[rowbase + r*NW]);
        float acc = 0.f;
#pragma unroll
        for (int n = 0; n < NP; n++) acc = fmaf(sEy[r*NP + n], rex[n], acc);
        float pm = p * m, tm = acc * m;
        float pn = (pm + EPSF) * invSp;
        float tn = (tm + EPSF) * invSt;
        float d  = pn - tn;
        g_diff[rowbase + r*NW] = d;
        sD[r*SDSTRIDE + skw] = d;
        klacc = fmaf(tn, __logf(__fdividef(tn, pn + EPSF)), klacc);
        ccol += (double)d;
        int fid = (seg*SEGROWS + r)*NW + w;
        if (pm > apv) { apv = pm; api = fid; }
        if (tm > atv) { atv = tm; ati = fid; }
    }
    g_colseg[blk*NW + w] = ccol;
    __syncthreads();

    /* --- EMD-W: warp `wid` scans row `wid`; lane owns 16 contiguous elems.
           All cumulative sums in fp64 (heavy cancellation in pn-tn cumsum). --- */
    double ewacc = 0.0;
    {
        float vals[16];
        int base = wid*SDSTRIDE + lane*17;
        double s = 0.0;
#pragma unroll
        for (int i = 0; i < 16; i++) { vals[i] = sD[base + i]; s += (double)vals[i]; }
        double incl = s;
#pragma unroll
        for (int off = 1; off < 32; off <<= 1) {
            double u = __shfl_up_sync(~0u, incl, off);
            if (lane >= off) incl += u;
        }
        double run = incl - s;                 /* exclusive prefix */
#pragma unroll
        for (int i = 0; i < 16; i++) { run += (double)vals[i]; ewacc += fabs(run); }
    }

    /* --- block reductions --- */
    float v = klacc;
#pragma unroll
    for (int off = 16; off; off >>= 1) v += __shfl_xor_sync(~0u, v, off);
    if (lane == 0) sred[wid] = v;
    __syncthreads();
    if (w == 0) { float s = 0.f;
#pragma unroll
        for (int j = 0; j < 16; j++) s += sred[j];
        g_part_kl[blk] = (double)s; }
    __syncthreads();

    double dv = ewacc;
#pragma unroll
    for (int off = 16; off; off >>= 1) dv += __shfl_xor_sync(~0u, dv, off);
    if (lane == 0) sredd[wid] = dv;
    __syncthreads();
    if (w == 0) { double s = 0.0;
#pragma unroll
        for (int j = 0; j < 16; j++) s += sredd[j];
        g_part_emdw[blk] = s; }
    __syncthreads();

    /* argmax pred (val desc, idx asc) */
    float av = apv; int ai = api;
#pragma unroll
    for (int off = 16; off; off >>= 1) {
        float ov = __shfl_xor_sync(~0u, av, off);
        int   oi = __shfl_xor_sync(~0u, ai, off);
        if (ov > av || (ov == av && oi < ai)) { av = ov; ai = oi; }
    }
    if (lane == 0) { sred[wid] = av; sidx[wid] = ai; }
    __syncthreads();
    if (w == 0) {
        float bv = sred[0]; int bi = sidx[0];
#pragma unroll
        for (int j = 1; j < 16; j++)
            if (sred[j] > bv || (sred[j] == bv && sidx[j] < bi)) { bv = sred[j]; bi = sidx[j]; }
        g_amax_pval[blk] = bv; g_amax_pidx[blk] = bi;
    }
    __syncthreads();

    /* argmax targ */
    av = atv; ai = ati;
#pragma unroll
    for (int off = 16; off; off >>= 1) {
        float ov = __shfl_xor_sync(~0u, av, off);
        int   oi = __shfl_xor_sync(~0u, ai, off);
        if (ov > av || (ov == av && oi < ai)) { av = ov; ai = oi; }
    }
    if (lane == 0) { sred[wid] = av; sidx[wid] = ai; }
    __syncthreads();
    if (w == 0) {
        float bv = sred[0]; int bi = sidx[0];
#pragma unroll
        for (int j = 1; j < 16; j++)
            if (sred[j] > bv || (sred[j] == bv && sidx[j] < bi)) { bv = sred[j]; bi = sidx[j]; }
        g_amax_tval[blk] = bv; g_amax_tidx[blk] = bi;
    }
}

/* ===== K4: EMD-along-H. Carry computed from <=31 INDEPENDENT loads
          (4 interleaved fp64 accumulators -> short dependency chains). ===== */
__global__ __launch_bounds__(512) void k_emdh() {
    int blk = blockIdx.x;                 /* b*NSEG+seg */
    int b = blk >> 5, seg = blk & 31;
    int w = threadIdx.x, lane = w & 31, wid = w >> 5;

    const double* cs = &g_colseg[b*NSEG*NW + w];
    double c0 = 0.0, c1 = 0.0, c2 = 0.0, c3 = 0.0;
#pragma unroll
    for (int s2 = 0; s2 < NSEG; s2 += 4) {
        if (s2 + 0 < seg) c0 += cs[(s2+0)*NW];
        if (s2 + 1 < seg) c1 += cs[(s2+1)*NW];
        if (s2 + 2 < seg) c2 += cs[(s2+2)*NW];
        if (s2 + 3 < seg) c3 += cs[(s2+3)*NW];
    }
    double c = (c0 + c1) + (c2 + c3);

    const float* dptr = &g_diff[(b*NH + seg*SEGROWS)*NW + w];
    double acc = 0.0;
#pragma unroll
    for (int r = 0; r < SEGROWS; r++) { c += (double)dptr[r*NW]; acc += fabs(c); }

#pragma unroll
    for (int off = 16; off; off >>= 1) acc += __shfl_xor_sync(~0u, acc, off);
    __shared__ double sredd[16];
    if (lane == 0) sredd[wid] = acc;
    __syncthreads();
    if (w == 0) { double s = 0.0;
#pragma unroll
        for (int j = 0; j < 16; j++) s += sredd[j];
        g_part_emdh[blk] = s; }
}

/* ===== K5: finalize ===== */
__global__ __launch_bounds__(256) void k_final(float* __restrict__ out, int out_size) {
    int t = threadIdx.x;                  /* 256 */
    int lane = t & 31, wid = t >> 5;
    __shared__ double sredd[8];
    __shared__ double res3[3];
    __shared__ float ppx[NB], ppy[NB], tpx[NB], tpy[NB];

    const double* srcs[3] = { g_part_kl, g_part_emdw, g_part_emdh };
    for (int k = 0; k < 3; k++) {
        double v = srcs[k][t];
#pragma unroll
        for (int off = 16; off; off >>= 1) v += __shfl_xor_sync(~0u, v, off);
        if (lane == 0) sredd[wid] = v;
        __syncthreads();
        if (t == 0) { double s = 0.0;
#pragma unroll
            for (int j = 0; j < 8; j++) s += sredd[j];
            res3[k] = s; }
        __syncthreads();
    }

    /* per-batch argmax: warp wid handles batch wid */
    {
        float av = g_amax_pval[t]; int ai = g_amax_pidx[t];
#pragma unroll
        for (int off = 16; off; off >>= 1) {
            float ov = __shfl_xor_sync(~0u, av, off);
            int   oi = __shfl_xor_sync(~0u, ai, off);
            if (ov > av || (ov == av && oi < ai)) { av = ov; ai = oi; }
        }
        if (lane == 0) {
            ppy[wid] = (float)(ai / NW) * (1.0f/511.0f);
            ppx[wid] = (float)(ai % NW) * (1.0f/511.0f);
        }
        av = g_amax_tval[t]; ai = g_amax_tidx[t];
#pragma unroll
        for (int off = 16; off; off >>= 1) {
            float ov = __shfl_xor_sync(~0u, av, off);
            int   oi = __shfl_xor_sync(~0u, ai, off);
            if (ov > av || (ov == av && oi < ai)) { av = ov; ai = oi; }
        }
        if (lane == 0) {
            tpy[wid] = (float)(ai / NW) * (1.0f/511.0f);
            tpx[wid] = (float)(ai % NW) * (1.0f/511.0f);
        }
    }
    __syncthreads();

    if (t == 0) {
        float loss = (float)(res3[0] * (1.0/(double)NB));
        float emd  = (float)((res3[1] + res3[2]) * (0.5 / ((double)NB * (double)HWC)));
        int cnt = 0;
        for (int b = 0; b < NB; b++) {
            float dx = ppx[b]-tpx[b], dy = ppy[b]-tpy[b];
            if (sqrtf(dx*dx + dy*dy) < 0.1f) cnt++;
        }
        float acc = (float)cnt * (1.0f/(float)NB);
        if (out_size > 0) out[0] = loss;
        if (out_size > 1) out[1] = emd;
        if (out_size > 2) out[2] = acc;
    }
}

extern "C" void kernel_launch(void* const* d_in, const int* in_sizes, int n_in,
                              void* d_out, int out_size) {
    const float* pred = (const float*)d_in[0];   /* [8,512,512] */
    const float* pts  = (const float*)d_in[1];   /* [8,32,2]    */
    const float* mask = (const float*)d_in[2];   /* [8]         */
    float* out = (float*)d_out;

    k_prep<<<NB*NP + NB*PSPLIT, 512>>>(pts, (const float4*)pred);
    k_norm<<<1, 32>>>(mask);
    k_main<<<NB*NSEG, 512>>>(pred, mask);
    k_emdh<<<NB*NSEG, 512>>>();
    k_final<<<1, 256>>>(out, out_size);
}